// round 2
// baseline (speedup 1.0000x reference)
#include <cuda_runtime.h>
#include <cuda_bf16.h>
#include <math.h>

#define N_NODES 50000
#define N_EDGES 800000
#define IN_CH   128
#define HID     256
#define MPAD    50048   // 391 * 128, padded M for GEMM tiles

// ---------------- scratch (device globals; zero-initialized bss) ----------------
__device__ int   g_is64;                  // 1 if edge_index is int64, 0 if int32
__device__ int   g_cnt[N_NODES];
__device__ int   g_rowptr[N_NODES + 1];
__device__ int   g_cursor[N_NODES];
__device__ int   g_col[N_EDGES];
__device__ float g_dinv[N_NODES];
__device__ float g_p[(size_t)MPAD * IN_CH];   // A_norm @ x          (pad rows stay 0)
__device__ float g_h[(size_t)MPAD * HID];     // relu(p@W1 + b1)
__device__ float g_q[(size_t)MPAD * HID];     // A_norm @ h          (pad rows stay 0)

// ---------------- dtype detection ----------------
__global__ void detect_kernel(const int* __restrict__ ei_raw) {
    // int64 little-endian with values in [0, 50000): every odd int32 word is 0.
    int ok = 1;
    for (int i = 1; i < 256; i += 2)
        if (ei_raw[i] != 0) { ok = 0; break; }
    g_is64 = ok;
}

__device__ __forceinline__ int load_edge(const void* ei, long long pos) {
    if (g_is64) return (int)((const long long*)ei)[pos];
    return ((const int*)ei)[pos];
}

// ---------------- graph preprocessing ----------------
__global__ void zero_cnt_kernel() {
    int i = blockIdx.x * blockDim.x + threadIdx.x;
    if (i < N_NODES) g_cnt[i] = 0;
}

__global__ void hist_kernel(const void* __restrict__ ei) {
    int e = blockIdx.x * blockDim.x + threadIdx.x;
    if (e < N_EDGES) {
        int d = load_edge(ei, (long long)N_EDGES + e);  // dst row
        atomicAdd(&g_cnt[d], 1);
    }
}

// single-block scan over 50000 counts: rowptr, cursor, dinv
__global__ void scan_kernel() {
    __shared__ int sums[1024];
    int tid = threadIdx.x;
    const int CH = (N_NODES + 1023) / 1024;  // 49
    int start = tid * CH;
    int end   = start + CH; if (end > N_NODES) end = N_NODES;
    if (start > N_NODES) start = N_NODES;

    int s = 0;
    for (int i = start; i < end; i++) s += g_cnt[i];
    sums[tid] = s;
    __syncthreads();
    // inclusive scan (Hillis-Steele)
    for (int off = 1; off < 1024; off <<= 1) {
        int v = (tid >= off) ? sums[tid - off] : 0;
        __syncthreads();
        sums[tid] += v;
        __syncthreads();
    }
    int run = sums[tid] - s;  // exclusive prefix for this chunk
    for (int i = start; i < end; i++) {
        g_rowptr[i] = run;
        g_cursor[i] = run;
        g_dinv[i]   = rsqrtf((float)(g_cnt[i] + 1));  // +1 self loop
        run += g_cnt[i];
    }
    if (tid == 0) g_rowptr[N_NODES] = N_EDGES;
}

__global__ void fill_kernel(const void* __restrict__ ei) {
    int e = blockIdx.x * blockDim.x + threadIdx.x;
    if (e < N_EDGES) {
        int s = load_edge(ei, e);                       // src row
        int d = load_edge(ei, (long long)N_EDGES + e);  // dst row
        int pos = atomicAdd(&g_cursor[d], 1);
        g_col[pos] = s;
    }
}

// ---------------- aggregation ----------------
// out[v] = dinv[v] * sum_{s in N(v)} dinv[s]*feat[s] + dinv[v]^2 * feat[v]
template <int F>
__global__ void __launch_bounds__(128)
agg_kernel(const float* __restrict__ feat, float* __restrict__ out) {
    constexpr int C = F / 128;
    __shared__ int   s_idx[32];
    __shared__ float s_w[32];
    int v   = blockIdx.x;
    int tid = threadIdx.x;
    int beg = g_rowptr[v];
    int end = g_rowptr[v + 1];

    float acc[C];
#pragma unroll
    for (int c = 0; c < C; c++) acc[c] = 0.f;

    for (int cs = beg; cs < end; cs += 32) {
        int n = end - cs; if (n > 32) n = 32;
        if (tid < n) {
            int s = g_col[cs + tid];
            s_idx[tid] = s;
            s_w[tid]   = g_dinv[s];
        }
        __syncthreads();
        for (int j = 0; j < n; j++) {
            const float* row = feat + (size_t)s_idx[j] * F;
            float w = s_w[j];
#pragma unroll
            for (int c = 0; c < C; c++) acc[c] += w * row[tid + 128 * c];
        }
        __syncthreads();
    }

    float dv = g_dinv[v];
    const float* self = feat + (size_t)v * F;
#pragma unroll
    for (int c = 0; c < C; c++)
        out[(size_t)v * F + tid + 128 * c] = dv * acc[c] + dv * dv * self[tid + 128 * c];
}

// ---------------- SGEMM: C[M,256] = A[MPAD,K] @ B[K,256] (+bias, optional relu) ----------------
// BM=128, BN=128, BK=8, 256 threads, 8x8 per thread, double-buffered smem
__global__ void __launch_bounds__(256)
sgemm_kernel(const float* __restrict__ A, const float* __restrict__ B,
             const float* __restrict__ bias, float* __restrict__ C,
             int K, int Mstore, int doRelu) {
    const int BM = 128, BN = 128, BK = 8;
    __shared__ float As[2][BK][BM];
    __shared__ float Bs[2][BK][BN];

    int tid  = threadIdx.x;
    int bx   = blockIdx.x;               // N tile: 0..1
    int by   = blockIdx.y;               // M tile: 0..390
    int row0 = by * BM, col0 = bx * BN;

    int a_row  = tid >> 1;               // 0..127
    int a_col4 = (tid & 1) * 4;          // 0 or 4
    int b_row  = tid >> 5;               // 0..7
    int b_col4 = (tid & 31) * 4;         // 0..124

    const float* Aptr = A + (size_t)(row0 + a_row) * K + a_col4;
    const float* Bptr = B + (size_t)b_row * 256 + col0 + b_col4;

    int ty = tid >> 4, tx = tid & 15;

    float acc[8][8];
#pragma unroll
    for (int i = 0; i < 8; i++)
#pragma unroll
        for (int j = 0; j < 8; j++) acc[i][j] = 0.f;

    // prologue: load tile 0 into buffer 0
    float4 a4 = *(const float4*)Aptr;
    float4 b4 = *(const float4*)Bptr;
    As[0][a_col4 + 0][a_row] = a4.x;
    As[0][a_col4 + 1][a_row] = a4.y;
    As[0][a_col4 + 2][a_row] = a4.z;
    As[0][a_col4 + 3][a_row] = a4.w;
    *(float4*)&Bs[0][b_row][b_col4] = b4;
    __syncthreads();

    int nk = K / BK;
    for (int kt = 0; kt < nk; kt++) {
        int cur = kt & 1, nxt = cur ^ 1;
        if (kt + 1 < nk) {
            a4 = *(const float4*)(Aptr + (kt + 1) * BK);
            b4 = *(const float4*)(Bptr + (size_t)(kt + 1) * BK * 256);
        }
#pragma unroll
        for (int k = 0; k < BK; k++) {
            float ra[8], rb[8];
            float4 t0 = *(const float4*)&As[cur][k][ty * 8 + 0];
            float4 t1 = *(const float4*)&As[cur][k][ty * 8 + 4];
            ra[0]=t0.x; ra[1]=t0.y; ra[2]=t0.z; ra[3]=t0.w;
            ra[4]=t1.x; ra[5]=t1.y; ra[6]=t1.z; ra[7]=t1.w;
            float4 u0 = *(const float4*)&Bs[cur][k][tx * 8 + 0];
            float4 u1 = *(const float4*)&Bs[cur][k][tx * 8 + 4];
            rb[0]=u0.x; rb[1]=u0.y; rb[2]=u0.z; rb[3]=u0.w;
            rb[4]=u1.x; rb[5]=u1.y; rb[6]=u1.z; rb[7]=u1.w;
#pragma unroll
            for (int i = 0; i < 8; i++)
#pragma unroll
                for (int j = 0; j < 8; j++)
                    acc[i][j] += ra[i] * rb[j];
        }
        if (kt + 1 < nk) {
            As[nxt][a_col4 + 0][a_row] = a4.x;
            As[nxt][a_col4 + 1][a_row] = a4.y;
            As[nxt][a_col4 + 2][a_row] = a4.z;
            As[nxt][a_col4 + 3][a_row] = a4.w;
            *(float4*)&Bs[nxt][b_row][b_col4] = b4;
            __syncthreads();
        }
    }

    // epilogue
#pragma unroll
    for (int i = 0; i < 8; i++) {
        int row = row0 + ty * 8 + i;
        if (row < Mstore) {
#pragma unroll
            for (int j = 0; j < 8; j += 4) {
                int col = col0 + tx * 8 + j;
                float4 v;
                v.x = acc[i][j + 0] + bias[col + 0];
                v.y = acc[i][j + 1] + bias[col + 1];
                v.z = acc[i][j + 2] + bias[col + 2];
                v.w = acc[i][j + 3] + bias[col + 3];
                if (doRelu) {
                    v.x = fmaxf(v.x, 0.f); v.y = fmaxf(v.y, 0.f);
                    v.z = fmaxf(v.z, 0.f); v.w = fmaxf(v.w, 0.f);
                }
                *(float4*)(C + (size_t)row * 256 + col) = v;
            }
        }
    }
}

// ---------------- launch ----------------
extern "C" void kernel_launch(void* const* d_in, const int* in_sizes, int n_in,
                              void* d_out, int out_size) {
    const float* x   = (const float*)d_in[0];
    const void*  ei  = d_in[1];                  // [2, N_EDGES] int32 OR int64
    const float* W1  = (const float*)d_in[2];
    const float* b1  = (const float*)d_in[3];
    const float* W2  = (const float*)d_in[4];
    const float* b2  = (const float*)d_in[5];
    float*       out = (float*)d_out;

    float *p, *h, *q;
    cudaGetSymbolAddress((void**)&p, g_p);
    cudaGetSymbolAddress((void**)&h, g_h);
    cudaGetSymbolAddress((void**)&q, g_q);

    // graph build
    detect_kernel<<<1, 1>>>((const int*)ei);
    zero_cnt_kernel<<<(N_NODES + 255) / 256, 256>>>();
    hist_kernel<<<(N_EDGES + 255) / 256, 256>>>(ei);
    scan_kernel<<<1, 1024>>>();
    fill_kernel<<<(N_EDGES + 255) / 256, 256>>>(ei);

    // layer 1: p = A_norm @ x ; h = relu(p @ W1 + b1)
    agg_kernel<IN_CH><<<N_NODES, 128>>>(x, p);
    sgemm_kernel<<<dim3(2, MPAD / 128), 256>>>(p, W1, b1, h, IN_CH, MPAD, 1);

    // layer 2: q = A_norm @ h ; out = q @ W2 + b2
    agg_kernel<HID><<<N_NODES, 128>>>(h, q);
    sgemm_kernel<<<dim3(2, MPAD / 128), 256>>>(q, W2, b2, out, HID, N_NODES, 0);
}

// round 3
// speedup vs baseline: 1.2305x; 1.2305x over previous
#include <cuda_runtime.h>
#include <cuda_bf16.h>
#include <math.h>

#define N_NODES 50000
#define N_EDGES 800000
#define IN_CH   128
#define HID     256
#define MPAD    50048   // 391 * 128, padded M for GEMM tiles
#define NBLK    ((N_NODES + 255) / 256)   // 196

// ---------------- scratch (device globals; zero-initialized bss) ----------------
__device__ int   g_is64;                  // 1 if edge_index is int64, 0 if int32
__device__ int   g_cnt[N_NODES];
__device__ int   g_bsum[NBLK];
__device__ int   g_boff[NBLK];
__device__ int   g_rowptr[N_NODES + 1];
__device__ int   g_cursor[N_NODES];
__device__ int   g_col[N_EDGES];
__device__ float g_dinv[N_NODES];
__device__ float g_p[(size_t)MPAD * IN_CH];   // A_norm @ x          (pad rows stay 0)
__device__ float g_h[(size_t)MPAD * HID];     // relu(p@W1 + b1)
__device__ float g_q[(size_t)MPAD * HID];     // A_norm @ h          (pad rows stay 0)

// ---------------- dtype detection (parallel) ----------------
__global__ void detect_kernel(const int* __restrict__ ei_raw) {
    // int64 little-endian with values in [0, 50000): every odd int32 word is 0.
    __shared__ int bad;
    if (threadIdx.x == 0) bad = 0;
    __syncthreads();
    if (ei_raw[2 * threadIdx.x + 1] != 0) bad = 1;   // benign race, any writer sets 1
    __syncthreads();
    if (threadIdx.x == 0) g_is64 = (bad == 0);
}

__device__ __forceinline__ int load_edge(const void* ei, long long pos) {
    if (g_is64) return (int)((const long long*)ei)[pos];
    return ((const int*)ei)[pos];
}

// ---------------- graph preprocessing ----------------
__global__ void zero_cnt_kernel() {
    int i = blockIdx.x * blockDim.x + threadIdx.x;
    if (i < N_NODES) g_cnt[i] = 0;
}

__global__ void hist_kernel(const void* __restrict__ ei) {
    int e = blockIdx.x * blockDim.x + threadIdx.x;
    if (e < N_EDGES) {
        int d = load_edge(ei, (long long)N_EDGES + e);  // dst row
        atomicAdd(&g_cnt[d], 1);
    }
}

// phase A: per-block sums of g_cnt
__global__ void __launch_bounds__(256) blocksum_kernel() {
    __shared__ int sh[256];
    int i = blockIdx.x * 256 + threadIdx.x;
    int v = (i < N_NODES) ? g_cnt[i] : 0;
    sh[threadIdx.x] = v;
    __syncthreads();
    for (int off = 128; off > 0; off >>= 1) {
        if (threadIdx.x < off) sh[threadIdx.x] += sh[threadIdx.x + off];
        __syncthreads();
    }
    if (threadIdx.x == 0) g_bsum[blockIdx.x] = sh[0];
}

// phase B: one-block exclusive scan over the NBLK partial sums
__global__ void __launch_bounds__(256) scanb_kernel() {
    __shared__ int sh[256];
    int t = threadIdx.x;
    int v = (t < NBLK) ? g_bsum[t] : 0;
    sh[t] = v;
    __syncthreads();
    for (int off = 1; off < 256; off <<= 1) {
        int u = (t >= off) ? sh[t - off] : 0;
        __syncthreads();
        sh[t] += u;
        __syncthreads();
    }
    if (t < NBLK) g_boff[t] = sh[t] - v;   // exclusive prefix
}

// phase C: per-block local prefix + write rowptr/cursor/dinv
__global__ void __launch_bounds__(256) fillptr_kernel() {
    __shared__ int sh[256];
    int i = blockIdx.x * 256 + threadIdx.x;
    int c = (i < N_NODES) ? g_cnt[i] : 0;
    sh[threadIdx.x] = c;
    __syncthreads();
    for (int off = 1; off < 256; off <<= 1) {
        int u = (threadIdx.x >= off) ? sh[threadIdx.x - off] : 0;
        __syncthreads();
        sh[threadIdx.x] += u;
        __syncthreads();
    }
    if (i < N_NODES) {
        int excl = sh[threadIdx.x] - c + g_boff[blockIdx.x];
        g_rowptr[i] = excl;
        g_cursor[i] = excl;
        g_dinv[i]   = rsqrtf((float)(c + 1));   // +1 self loop
    }
    if (i == 0) g_rowptr[N_NODES] = N_EDGES;
}

__global__ void fill_kernel(const void* __restrict__ ei) {
    int e = blockIdx.x * blockDim.x + threadIdx.x;
    if (e < N_EDGES) {
        int s = load_edge(ei, e);                       // src row
        int d = load_edge(ei, (long long)N_EDGES + e);  // dst row
        int pos = atomicAdd(&g_cursor[d], 1);
        g_col[pos] = s;
    }
}

// ---------------- aggregation ----------------
// out[v] = dinv[v] * sum_{s in N(v)} dinv[s]*feat[s] + dinv[v]^2 * feat[v]
template <int F>
__global__ void __launch_bounds__(128)
agg_kernel(const float* __restrict__ feat, float* __restrict__ out) {
    constexpr int C = F / 128;
    __shared__ int   s_idx[32];
    __shared__ float s_w[32];
    int v   = blockIdx.x;
    int tid = threadIdx.x;
    int beg = g_rowptr[v];
    int end = g_rowptr[v + 1];

    float acc[C];
#pragma unroll
    for (int c = 0; c < C; c++) acc[c] = 0.f;

    for (int cs = beg; cs < end; cs += 32) {
        int n = end - cs; if (n > 32) n = 32;
        if (tid < n) {
            int s = g_col[cs + tid];
            s_idx[tid] = s;
            s_w[tid]   = g_dinv[s];
        }
        __syncthreads();
        for (int j = 0; j < n; j++) {
            const float* row = feat + (size_t)s_idx[j] * F;
            float w = s_w[j];
#pragma unroll
            for (int c = 0; c < C; c++) acc[c] += w * row[tid + 128 * c];
        }
        __syncthreads();
    }

    float dv = g_dinv[v];
    const float* self = feat + (size_t)v * F;
#pragma unroll
    for (int c = 0; c < C; c++)
        out[(size_t)v * F + tid + 128 * c] = dv * acc[c] + dv * dv * self[tid + 128 * c];
}

// ---------------- SGEMM: C[M,256] = A[MPAD,K] @ B[K,256] (+bias, optional relu) ----------------
// BM=128, BN=128, BK=8, 256 threads, 8x8 per thread, double-buffered smem
__global__ void __launch_bounds__(256)
sgemm_kernel(const float* __restrict__ A, const float* __restrict__ B,
             const float* __restrict__ bias, float* __restrict__ C,
             int K, int Mstore, int doRelu) {
    const int BM = 128, BN = 128, BK = 8;
    __shared__ float As[2][BK][BM];
    __shared__ float Bs[2][BK][BN];

    int tid  = threadIdx.x;
    int bx   = blockIdx.x;               // N tile: 0..1
    int by   = blockIdx.y;               // M tile: 0..390
    int row0 = by * BM, col0 = bx * BN;

    int a_row  = tid >> 1;               // 0..127
    int a_col4 = (tid & 1) * 4;          // 0 or 4
    int b_row  = tid >> 5;               // 0..7
    int b_col4 = (tid & 31) * 4;         // 0..124

    const float* Aptr = A + (size_t)(row0 + a_row) * K + a_col4;
    const float* Bptr = B + (size_t)b_row * 256 + col0 + b_col4;

    int ty = tid >> 4, tx = tid & 15;

    float acc[8][8];
#pragma unroll
    for (int i = 0; i < 8; i++)
#pragma unroll
        for (int j = 0; j < 8; j++) acc[i][j] = 0.f;

    // prologue: load tile 0 into buffer 0
    float4 a4 = *(const float4*)Aptr;
    float4 b4 = *(const float4*)Bptr;
    As[0][a_col4 + 0][a_row] = a4.x;
    As[0][a_col4 + 1][a_row] = a4.y;
    As[0][a_col4 + 2][a_row] = a4.z;
    As[0][a_col4 + 3][a_row] = a4.w;
    *(float4*)&Bs[0][b_row][b_col4] = b4;
    __syncthreads();

    int nk = K / BK;
    for (int kt = 0; kt < nk; kt++) {
        int cur = kt & 1, nxt = cur ^ 1;
        if (kt + 1 < nk) {
            a4 = *(const float4*)(Aptr + (kt + 1) * BK);
            b4 = *(const float4*)(Bptr + (size_t)(kt + 1) * BK * 256);
        }
#pragma unroll
        for (int k = 0; k < BK; k++) {
            float ra[8], rb[8];
            float4 t0 = *(const float4*)&As[cur][k][ty * 8 + 0];
            float4 t1 = *(const float4*)&As[cur][k][ty * 8 + 4];
            ra[0]=t0.x; ra[1]=t0.y; ra[2]=t0.z; ra[3]=t0.w;
            ra[4]=t1.x; ra[5]=t1.y; ra[6]=t1.z; ra[7]=t1.w;
            float4 u0 = *(const float4*)&Bs[cur][k][tx * 8 + 0];
            float4 u1 = *(const float4*)&Bs[cur][k][tx * 8 + 4];
            rb[0]=u0.x; rb[1]=u0.y; rb[2]=u0.z; rb[3]=u0.w;
            rb[4]=u1.x; rb[5]=u1.y; rb[6]=u1.z; rb[7]=u1.w;
#pragma unroll
            for (int i = 0; i < 8; i++)
#pragma unroll
                for (int j = 0; j < 8; j++)
                    acc[i][j] += ra[i] * rb[j];
        }
        if (kt + 1 < nk) {
            As[nxt][a_col4 + 0][a_row] = a4.x;
            As[nxt][a_col4 + 1][a_row] = a4.y;
            As[nxt][a_col4 + 2][a_row] = a4.z;
            As[nxt][a_col4 + 3][a_row] = a4.w;
            *(float4*)&Bs[nxt][b_row][b_col4] = b4;
            __syncthreads();
        }
    }

    // epilogue
#pragma unroll
    for (int i = 0; i < 8; i++) {
        int row = row0 + ty * 8 + i;
        if (row < Mstore) {
#pragma unroll
            for (int j = 0; j < 8; j += 4) {
                int col = col0 + tx * 8 + j;
                float4 v;
                v.x = acc[i][j + 0] + bias[col + 0];
                v.y = acc[i][j + 1] + bias[col + 1];
                v.z = acc[i][j + 2] + bias[col + 2];
                v.w = acc[i][j + 3] + bias[col + 3];
                if (doRelu) {
                    v.x = fmaxf(v.x, 0.f); v.y = fmaxf(v.y, 0.f);
                    v.z = fmaxf(v.z, 0.f); v.w = fmaxf(v.w, 0.f);
                }
                *(float4*)(C + (size_t)row * 256 + col) = v;
            }
        }
    }
}

// ---------------- launch ----------------
extern "C" void kernel_launch(void* const* d_in, const int* in_sizes, int n_in,
                              void* d_out, int out_size) {
    const float* x   = (const float*)d_in[0];
    const void*  ei  = d_in[1];                  // [2, N_EDGES] int32 OR int64
    const float* W1  = (const float*)d_in[2];
    const float* b1  = (const float*)d_in[3];
    const float* W2  = (const float*)d_in[4];
    const float* b2  = (const float*)d_in[5];
    float*       out = (float*)d_out;

    float *p, *h, *q;
    cudaGetSymbolAddress((void**)&p, g_p);
    cudaGetSymbolAddress((void**)&h, g_h);
    cudaGetSymbolAddress((void**)&q, g_q);

    // graph build
    detect_kernel<<<1, 128>>>((const int*)ei);
    zero_cnt_kernel<<<(N_NODES + 255) / 256, 256>>>();
    hist_kernel<<<(N_EDGES + 255) / 256, 256>>>(ei);
    blocksum_kernel<<<NBLK, 256>>>();
    scanb_kernel<<<1, 256>>>();
    fillptr_kernel<<<NBLK, 256>>>();
    fill_kernel<<<(N_EDGES + 255) / 256, 256>>>(ei);

    // layer 1: p = A_norm @ x ; h = relu(p @ W1 + b1)
    agg_kernel<IN_CH><<<N_NODES, 128>>>(x, p);
    sgemm_kernel<<<dim3(2, MPAD / 128), 256>>>(p, W1, b1, h, IN_CH, MPAD, 1);

    // layer 2: q = A_norm @ h ; out = q @ W2 + b2
    agg_kernel<HID><<<N_NODES, 128>>>(h, q);
    sgemm_kernel<<<dim3(2, MPAD / 128), 256>>>(q, W2, b2, out, HID, N_NODES, 0);
}

// round 4
// speedup vs baseline: 1.7244x; 1.4014x over previous
#include <cuda_runtime.h>
#include <cuda_bf16.h>
#include <math.h>

#define N_NODES 50000
#define N_EDGES 800000
#define IN_CH   128
#define HID     256
#define MPAD    50048   // 391 * 128
#define NBLK    ((N_NODES + 255) / 256)   // 196

typedef __nv_bfloat16 bf16;

// ---------------- scratch (device globals; zero-initialized bss) ----------------
__device__ int   g_is64;
__device__ int   g_cnt[N_NODES];
__device__ int   g_bsum[NBLK];
__device__ int   g_boff[NBLK];
__device__ int   g_rowptr[N_NODES + 1];
__device__ int   g_cursor[N_NODES];
__device__ int   g_col[N_EDGES];
__device__ float g_dinv[N_NODES];

__device__ bf16  g_phi[(size_t)MPAD * IN_CH];   // split A for GEMM1 (pad rows stay 0)
__device__ bf16  g_plo[(size_t)MPAD * IN_CH];
__device__ float g_h[(size_t)MPAD * HID];       // relu(p@W1 + b1), fp32 for agg2
__device__ bf16  g_qhi[(size_t)MPAD * HID];     // split A for GEMM2
__device__ bf16  g_qlo[(size_t)MPAD * HID];

__device__ bf16  g_w1hi[HID * IN_CH];           // W1^T n-major [256][128]
__device__ bf16  g_w1lo[HID * IN_CH];
__device__ bf16  g_w2hi[HID * HID];             // W2^T n-major [256][256]
__device__ bf16  g_w2lo[HID * HID];

// ---------------- dtype detection ----------------
__global__ void detect_kernel(const int* __restrict__ ei_raw) {
    __shared__ int bad;
    if (threadIdx.x == 0) bad = 0;
    __syncthreads();
    if (ei_raw[2 * threadIdx.x + 1] != 0) bad = 1;
    __syncthreads();
    if (threadIdx.x == 0) g_is64 = (bad == 0);
}

__device__ __forceinline__ int load_edge(const void* ei, long long pos) {
    if (g_is64) return (int)((const long long*)ei)[pos];
    return ((const int*)ei)[pos];
}

// ---------------- graph preprocessing ----------------
__global__ void zero_cnt_kernel() {
    int i = blockIdx.x * blockDim.x + threadIdx.x;
    if (i < N_NODES) g_cnt[i] = 0;
}

__global__ void hist_kernel(const void* __restrict__ ei) {
    int e = blockIdx.x * blockDim.x + threadIdx.x;
    if (e < N_EDGES) atomicAdd(&g_cnt[load_edge(ei, (long long)N_EDGES + e)], 1);
}

__global__ void __launch_bounds__(256) blocksum_kernel() {
    __shared__ int sh[256];
    int i = blockIdx.x * 256 + threadIdx.x;
    int v = (i < N_NODES) ? g_cnt[i] : 0;
    sh[threadIdx.x] = v;
    __syncthreads();
    for (int off = 128; off > 0; off >>= 1) {
        if (threadIdx.x < off) sh[threadIdx.x] += sh[threadIdx.x + off];
        __syncthreads();
    }
    if (threadIdx.x == 0) g_bsum[blockIdx.x] = sh[0];
}

__global__ void __launch_bounds__(256) scanb_kernel() {
    __shared__ int sh[256];
    int t = threadIdx.x;
    int v = (t < NBLK) ? g_bsum[t] : 0;
    sh[t] = v;
    __syncthreads();
    for (int off = 1; off < 256; off <<= 1) {
        int u = (t >= off) ? sh[t - off] : 0;
        __syncthreads();
        sh[t] += u;
        __syncthreads();
    }
    if (t < NBLK) g_boff[t] = sh[t] - v;
}

__global__ void __launch_bounds__(256) fillptr_kernel() {
    __shared__ int sh[256];
    int i = blockIdx.x * 256 + threadIdx.x;
    int c = (i < N_NODES) ? g_cnt[i] : 0;
    sh[threadIdx.x] = c;
    __syncthreads();
    for (int off = 1; off < 256; off <<= 1) {
        int u = (threadIdx.x >= off) ? sh[threadIdx.x - off] : 0;
        __syncthreads();
        sh[threadIdx.x] += u;
        __syncthreads();
    }
    if (i < N_NODES) {
        int excl = sh[threadIdx.x] - c + g_boff[blockIdx.x];
        g_rowptr[i] = excl;
        g_cursor[i] = excl;
        g_dinv[i]   = rsqrtf((float)(c + 1));
    }
    if (i == 0) g_rowptr[N_NODES] = N_EDGES;
}

__global__ void fill_kernel(const void* __restrict__ ei) {
    int e = blockIdx.x * blockDim.x + threadIdx.x;
    if (e < N_EDGES) {
        int s = load_edge(ei, e);
        int d = load_edge(ei, (long long)N_EDGES + e);
        int pos = atomicAdd(&g_cursor[d], 1);
        g_col[pos] = s;
    }
}

// ---------------- W split+transpose: W [K][256] fp32 -> Bhi/Blo [256][K] bf16 ----------------
__global__ void splitW_kernel(const float* __restrict__ W, int K,
                              bf16* __restrict__ Bhi, bf16* __restrict__ Blo) {
    int idx = blockIdx.x * 256 + threadIdx.x;
    if (idx < K * 256) {
        int k = idx >> 8, n = idx & 255;
        float v = W[idx];
        bf16 h = __float2bfloat16(v);
        float lo = v - __bfloat162float(h);
        Bhi[n * K + k] = h;
        Blo[n * K + k] = __float2bfloat16(lo);
    }
}

// ---------------- aggregation: out hi/lo bf16 split ----------------
// val[v] = dinv[v] * sum_{s in N(v)} dinv[s]*feat[s] + dinv[v]^2 * feat[v]
template <int F>
__global__ void __launch_bounds__(128)
agg_kernel(const float* __restrict__ feat, bf16* __restrict__ ohi, bf16* __restrict__ olo) {
    constexpr int C = F / 128;
    __shared__ int   s_idx[32];
    __shared__ float s_w[32];
    int v   = blockIdx.x;
    int tid = threadIdx.x;
    int beg = g_rowptr[v];
    int end = g_rowptr[v + 1];

    float acc[C];
#pragma unroll
    for (int c = 0; c < C; c++) acc[c] = 0.f;

    for (int cs = beg; cs < end; cs += 32) {
        int n = end - cs; if (n > 32) n = 32;
        if (tid < n) {
            int s = g_col[cs + tid];
            s_idx[tid] = s;
            s_w[tid]   = g_dinv[s];
        }
        __syncthreads();
        for (int j = 0; j < n; j++) {
            const float* row = feat + (size_t)s_idx[j] * F;
            float w = s_w[j];
#pragma unroll
            for (int c = 0; c < C; c++) acc[c] += w * row[tid + 128 * c];
        }
        __syncthreads();
    }

    float dv = g_dinv[v];
    const float* self = feat + (size_t)v * F;
#pragma unroll
    for (int c = 0; c < C; c++) {
        size_t idx = (size_t)v * F + tid + 128 * c;
        float val = dv * acc[c] + dv * dv * self[tid + 128 * c];
        bf16 h = __float2bfloat16(val);
        ohi[idx] = h;
        olo[idx] = __float2bfloat16(val - __bfloat162float(h));
    }
}

// ---------------- tensor-core GEMM: C[M,256] = A[M,K] @ B^T[256,K] (+bias, relu) ----------------
// A split hi/lo [M][K] bf16; B split hi/lo n-major [256][K] bf16.
// 3-pass split MMA: hi*hi + hi*lo + lo*hi  (fp32 accum)
// Block 128x128, BK=32, 8 warps (4m x 2n), warp tile 32x64, mma m16n8k16.
#define MMA_BF16(acc, a, b) \
    asm volatile("mma.sync.aligned.m16n8k16.row.col.f32.bf16.bf16.f32 " \
                 "{%0,%1,%2,%3},{%4,%5,%6,%7},{%8,%9},{%0,%1,%2,%3};" \
                 : "+f"(acc[0]), "+f"(acc[1]), "+f"(acc[2]), "+f"(acc[3]) \
                 : "r"(a[0]), "r"(a[1]), "r"(a[2]), "r"(a[3]), "r"(b[0]), "r"(b[1]))

template <int K>
__global__ void __launch_bounds__(256, 2)
mma_gemm_kernel(const bf16* __restrict__ Ahi, const bf16* __restrict__ Alo,
                const bf16* __restrict__ Bhi, const bf16* __restrict__ Blo,
                const float* __restrict__ bias, float* __restrict__ C,
                int Mstore, int doRelu) {
    // smem: rows of 32 bf16 padded to 40 (80B stride -> conflict-free frag loads)
    __shared__ bf16 sA[2][128][40];   // [hi/lo][m][k]
    __shared__ bf16 sB[2][128][40];   // [hi/lo][n][k]

    int tid  = threadIdx.x;
    int lane = tid & 31;
    int warp = tid >> 5;
    int wm = warp >> 1, wn = warp & 1;     // 4 x 2 warp grid
    int g = lane >> 2, c = lane & 3;

    int row0 = blockIdx.y * 128;
    int col0 = blockIdx.x * 128;

    int ldrow = tid >> 1;          // 0..127
    int ldhalf = tid & 1;          // 16 bf16 halves

    float acc[2][8][4];
#pragma unroll
    for (int i = 0; i < 2; i++)
#pragma unroll
        for (int j = 0; j < 8; j++)
#pragma unroll
            for (int t = 0; t < 4; t++) acc[i][j][t] = 0.f;

    const int NST = K / 32;
    for (int s = 0; s < NST; s++) {
        if (s) __syncthreads();
        // load stage: each thread 16 bf16 (2x uint4) from each of Ahi/Alo/Bhi/Blo
        {
            size_t ga = (size_t)(row0 + ldrow) * K + s * 32 + ldhalf * 16;
            size_t gb = (size_t)(col0 + ldrow) * K + s * 32 + ldhalf * 16;
            const uint4* pAh = (const uint4*)(Ahi + ga);
            const uint4* pAl = (const uint4*)(Alo + ga);
            const uint4* pBh = (const uint4*)(Bhi + gb);
            const uint4* pBl = (const uint4*)(Blo + gb);
            uint4* dAh = (uint4*)&sA[0][ldrow][ldhalf * 16];
            uint4* dAl = (uint4*)&sA[1][ldrow][ldhalf * 16];
            uint4* dBh = (uint4*)&sB[0][ldrow][ldhalf * 16];
            uint4* dBl = (uint4*)&sB[1][ldrow][ldhalf * 16];
            dAh[0] = pAh[0]; dAh[1] = pAh[1];
            dAl[0] = pAl[0]; dAl[1] = pAl[1];
            dBh[0] = pBh[0]; dBh[1] = pBh[1];
            dBl[0] = pBl[0]; dBl[1] = pBl[1];
        }
        __syncthreads();

#pragma unroll
        for (int ks = 0; ks < 2; ks++) {
            int kb = ks * 16 + c * 2;
            unsigned ah[2][4], al[2][4];
#pragma unroll
            for (int i = 0; i < 2; i++) {
                const bf16* pa = &sA[0][wm * 32 + i * 16 + g][kb];
                ah[i][0] = *(const unsigned*)pa;
                ah[i][1] = *(const unsigned*)(pa + 8 * 40);
                ah[i][2] = *(const unsigned*)(pa + 8);
                ah[i][3] = *(const unsigned*)(pa + 8 * 40 + 8);
                const bf16* pl = &sA[1][wm * 32 + i * 16 + g][kb];
                al[i][0] = *(const unsigned*)pl;
                al[i][1] = *(const unsigned*)(pl + 8 * 40);
                al[i][2] = *(const unsigned*)(pl + 8);
                al[i][3] = *(const unsigned*)(pl + 8 * 40 + 8);
            }
#pragma unroll
            for (int j = 0; j < 8; j++) {
                const bf16* pb = &sB[0][wn * 64 + j * 8 + g][kb];
                unsigned bh[2], bl[2];
                bh[0] = *(const unsigned*)pb;
                bh[1] = *(const unsigned*)(pb + 8);
                const bf16* pbl = &sB[1][wn * 64 + j * 8 + g][kb];
                bl[0] = *(const unsigned*)pbl;
                bl[1] = *(const unsigned*)(pbl + 8);
#pragma unroll
                for (int i = 0; i < 2; i++) {
                    MMA_BF16(acc[i][j], ah[i], bh);
                    MMA_BF16(acc[i][j], ah[i], bl);
                    MMA_BF16(acc[i][j], al[i], bh);
                }
            }
        }
    }

    // epilogue
#pragma unroll
    for (int i = 0; i < 2; i++) {
        int r0 = row0 + wm * 32 + i * 16 + g;
        int r1 = r0 + 8;
#pragma unroll
        for (int j = 0; j < 8; j++) {
            int col = col0 + wn * 64 + j * 8 + c * 2;
            float bx = bias[col], by = bias[col + 1];
            float2 v0 = make_float2(acc[i][j][0] + bx, acc[i][j][1] + by);
            float2 v1 = make_float2(acc[i][j][2] + bx, acc[i][j][3] + by);
            if (doRelu) {
                v0.x = fmaxf(v0.x, 0.f); v0.y = fmaxf(v0.y, 0.f);
                v1.x = fmaxf(v1.x, 0.f); v1.y = fmaxf(v1.y, 0.f);
            }
            if (r0 < Mstore) *(float2*)&C[(size_t)r0 * 256 + col] = v0;
            if (r1 < Mstore) *(float2*)&C[(size_t)r1 * 256 + col] = v1;
        }
    }
}

// ---------------- launch ----------------
extern "C" void kernel_launch(void* const* d_in, const int* in_sizes, int n_in,
                              void* d_out, int out_size) {
    const float* x   = (const float*)d_in[0];
    const void*  ei  = d_in[1];
    const float* W1  = (const float*)d_in[2];
    const float* b1  = (const float*)d_in[3];
    const float* W2  = (const float*)d_in[4];
    const float* b2  = (const float*)d_in[5];
    float*       out = (float*)d_out;

    bf16 *phi, *plo, *qhi, *qlo, *w1hi, *w1lo, *w2hi, *w2lo;
    float *h;
    cudaGetSymbolAddress((void**)&phi, g_phi);
    cudaGetSymbolAddress((void**)&plo, g_plo);
    cudaGetSymbolAddress((void**)&qhi, g_qhi);
    cudaGetSymbolAddress((void**)&qlo, g_qlo);
    cudaGetSymbolAddress((void**)&h,   g_h);
    cudaGetSymbolAddress((void**)&w1hi, g_w1hi);
    cudaGetSymbolAddress((void**)&w1lo, g_w1lo);
    cudaGetSymbolAddress((void**)&w2hi, g_w2hi);
    cudaGetSymbolAddress((void**)&w2lo, g_w2lo);

    // graph build + weight split
    detect_kernel<<<1, 128>>>((const int*)ei);
    zero_cnt_kernel<<<(N_NODES + 255) / 256, 256>>>();
    hist_kernel<<<(N_EDGES + 255) / 256, 256>>>(ei);
    splitW_kernel<<<(IN_CH * 256 + 255) / 256, 256>>>(W1, IN_CH, w1hi, w1lo);
    splitW_kernel<<<(HID * 256 + 255) / 256, 256>>>(W2, HID, w2hi, w2lo);
    blocksum_kernel<<<NBLK, 256>>>();
    scanb_kernel<<<1, 256>>>();
    fillptr_kernel<<<NBLK, 256>>>();
    fill_kernel<<<(N_EDGES + 255) / 256, 256>>>(ei);

    // layer 1: p = A_norm @ x (split) ; h = relu(p @ W1 + b1)
    agg_kernel<IN_CH><<<N_NODES, 128>>>(x, phi, plo);
    mma_gemm_kernel<IN_CH><<<dim3(2, MPAD / 128), 256>>>(phi, plo, w1hi, w1lo, b1, h, MPAD, 1);

    // layer 2: q = A_norm @ h (split) ; out = q @ W2 + b2
    agg_kernel<HID><<<N_NODES, 128>>>(h, qhi, qlo);
    mma_gemm_kernel<HID><<<dim3(2, MPAD / 128), 256>>>(qhi, qlo, w2hi, w2lo, b2, out, N_NODES, 0);
}

// round 6
// speedup vs baseline: 1.7899x; 1.0380x over previous
#include <cuda_runtime.h>
#include <cuda_bf16.h>
#include <math.h>
#include <stdint.h>

#define N_NODES 50000
#define N_EDGES 800000
#define IN_CH   128
#define HID     256
#define MPAD    50048   // 391 * 128
#define NBLK    ((N_NODES + 255) / 256)   // 196

typedef __nv_bfloat16 bf16;

// ---------------- scratch (device globals; zero-initialized bss) ----------------
__device__ int   g_is64;
__device__ int   g_cnt[N_NODES];
__device__ int   g_bsum[NBLK];
__device__ int   g_boff[NBLK];
__device__ int   g_rowptr[N_NODES + 1];
__device__ int   g_cursor[N_NODES];
__device__ int   g_col[N_EDGES];
__device__ float g_dinv[N_NODES];

// K-extended split operands: A_ext = [hi | lo | hi], B_ext = [hi | hi | lo]
__device__ bf16  g_a1[(size_t)MPAD * (3 * IN_CH)];  // layer-1 A (pad rows stay 0)
__device__ bf16  g_a2[(size_t)MPAD * (3 * HID)];    // layer-2 A (pad rows stay 0)
__device__ float g_h[(size_t)MPAD * HID];           // relu(p@W1+b1) fp32
__device__ bf16  g_w1e[HID * (3 * IN_CH)];          // W1^T ext  [256][384]
__device__ bf16  g_w2e[HID * (3 * HID)];            // W2^T ext  [256][768]

// ---------------- helpers ----------------
__device__ __forceinline__ uint32_t smem_to_u32(const void* p) {
    uint32_t a;
    asm("{ .reg .u64 t; cvta.to.shared.u64 t, %1; cvt.u32.u64 %0, t; }" : "=r"(a) : "l"(p));
    return a;
}
#define CP_ASYNC16(dst, src) \
    asm volatile("cp.async.cg.shared.global [%0], [%1], 16;" :: "r"(dst), "l"(src))
#define CP_COMMIT() asm volatile("cp.async.commit_group;" ::: "memory")
#define CP_WAIT1()  asm volatile("cp.async.wait_group 1;" ::: "memory")

#define MMA_BF16(acc, a, b) \
    asm volatile("mma.sync.aligned.m16n8k16.row.col.f32.bf16.bf16.f32 " \
                 "{%0,%1,%2,%3},{%4,%5,%6,%7},{%8,%9},{%0,%1,%2,%3};" \
                 : "+f"(acc[0]), "+f"(acc[1]), "+f"(acc[2]), "+f"(acc[3]) \
                 : "r"(a[0]), "r"(a[1]), "r"(a[2]), "r"(a[3]), "r"(b[0]), "r"(b[1]))

// ---------------- dtype detection ----------------
__global__ void detect_kernel(const int* __restrict__ ei_raw) {
    __shared__ int bad;
    if (threadIdx.x == 0) bad = 0;
    __syncthreads();
    if (ei_raw[2 * threadIdx.x + 1] != 0) bad = 1;
    __syncthreads();
    if (threadIdx.x == 0) g_is64 = (bad == 0);
}
__device__ __forceinline__ int load_edge(const void* ei, long long pos) {
    if (g_is64) return (int)((const long long*)ei)[pos];
    return ((const int*)ei)[pos];
}

// ---------------- graph preprocessing ----------------
__global__ void zero_cnt_kernel() {
    int i = blockIdx.x * blockDim.x + threadIdx.x;
    if (i < N_NODES) g_cnt[i] = 0;
}
__global__ void hist_kernel(const void* __restrict__ ei) {
    int e = blockIdx.x * blockDim.x + threadIdx.x;
    if (e < N_EDGES) atomicAdd(&g_cnt[load_edge(ei, (long long)N_EDGES + e)], 1);
}
__global__ void __launch_bounds__(256) blocksum_kernel() {
    __shared__ int sh[256];
    int i = blockIdx.x * 256 + threadIdx.x;
    int v = (i < N_NODES) ? g_cnt[i] : 0;
    sh[threadIdx.x] = v;
    __syncthreads();
    for (int off = 128; off > 0; off >>= 1) {
        if (threadIdx.x < off) sh[threadIdx.x] += sh[threadIdx.x + off];
        __syncthreads();
    }
    if (threadIdx.x == 0) g_bsum[blockIdx.x] = sh[0];
}
__global__ void __launch_bounds__(256) scanb_kernel() {
    __shared__ int sh[256];
    int t = threadIdx.x;
    int v = (t < NBLK) ? g_bsum[t] : 0;
    sh[t] = v;
    __syncthreads();
    for (int off = 1; off < 256; off <<= 1) {
        int u = (t >= off) ? sh[t - off] : 0;
        __syncthreads();
        sh[t] += u;
        __syncthreads();
    }
    if (t < NBLK) g_boff[t] = sh[t] - v;
}
__global__ void __launch_bounds__(256) fillptr_kernel() {
    __shared__ int sh[256];
    int i = blockIdx.x * 256 + threadIdx.x;
    int c = (i < N_NODES) ? g_cnt[i] : 0;
    sh[threadIdx.x] = c;
    __syncthreads();
    for (int off = 1; off < 256; off <<= 1) {
        int u = (threadIdx.x >= off) ? sh[threadIdx.x - off] : 0;
        __syncthreads();
        sh[threadIdx.x] += u;
        __syncthreads();
    }
    if (i < N_NODES) {
        int excl = sh[threadIdx.x] - c + g_boff[blockIdx.x];
        g_rowptr[i] = excl;
        g_cursor[i] = excl;
        g_dinv[i]   = rsqrtf((float)(c + 1));
    }
    if (i == 0) g_rowptr[N_NODES] = N_EDGES;
}
__global__ void fill_kernel(const void* __restrict__ ei) {
    int e = blockIdx.x * blockDim.x + threadIdx.x;
    if (e < N_EDGES) {
        int s = load_edge(ei, e);
        int d = load_edge(ei, (long long)N_EDGES + e);
        int pos = atomicAdd(&g_cursor[d], 1);
        g_col[pos] = s;
    }
}

// ---------------- W split -> B_ext: W [K][256] fp32 -> Bex [256][3K] bf16 ----------------
__global__ void splitW_kernel(const float* __restrict__ W, int K, bf16* __restrict__ Bex) {
    int idx = blockIdx.x * 256 + threadIdx.x;
    if (idx < K * 256) {
        int k = idx >> 8, n = idx & 255;
        float v = W[idx];
        bf16 h = __float2bfloat16(v);
        bf16 l = __float2bfloat16(v - __bfloat162float(h));
        size_t rb = (size_t)n * 3 * K;
        Bex[rb + k]         = h;
        Bex[rb + K + k]     = h;
        Bex[rb + 2 * K + k] = l;
    }
}

// ---------------- aggregation -> A_ext [hi | lo | hi] ----------------
template <int F>
__global__ void __launch_bounds__(128)
agg_kernel(const float* __restrict__ feat, bf16* __restrict__ Aex) {
    constexpr int C = F / 128;
    __shared__ int   s_idx[32];
    __shared__ float s_w[32];
    int v   = blockIdx.x;
    int tid = threadIdx.x;
    int beg = g_rowptr[v];
    int end = g_rowptr[v + 1];

    float acc[C];
#pragma unroll
    for (int c = 0; c < C; c++) acc[c] = 0.f;

    for (int cs = beg; cs < end; cs += 32) {
        int n = end - cs; if (n > 32) n = 32;
        if (tid < n) {
            int s = g_col[cs + tid];
            s_idx[tid] = s;
            s_w[tid]   = g_dinv[s];
        }
        __syncthreads();
        for (int j = 0; j < n; j++) {
            const float* row = feat + (size_t)s_idx[j] * F;
            float w = s_w[j];
#pragma unroll
            for (int c = 0; c < C; c++) acc[c] += w * row[tid + 128 * c];
        }
        __syncthreads();
    }

    float dv = g_dinv[v];
    const float* self = feat + (size_t)v * F;
    size_t rb = (size_t)v * (3 * F);
#pragma unroll
    for (int c = 0; c < C; c++) {
        int k = tid + 128 * c;
        float val = dv * acc[c] + dv * dv * self[k];
        bf16 h = __float2bfloat16(val);
        bf16 l = __float2bfloat16(val - __bfloat162float(h));
        Aex[rb + k]         = h;
        Aex[rb + F + k]     = l;
        Aex[rb + 2 * F + k] = h;
    }
}

// ---------------- pipelined mma.sync GEMM ----------------
// C[M,256] = A_ext[M,KE] @ B_ext^T[256,KE] (+bias, relu)
// Block 128x128, BK=32, 3-stage cp.async pipeline, 8 warps (4m x 2n),
// warp tile 32x64, mma m16n8k16. smem rows padded to 40 bf16 (conflict-free).
#define ROWP 40
#define STAGE_ELEMS (128 * ROWP)      // per operand per stage

template <int KE>
__device__ __forceinline__ void gemm_issue(const bf16* __restrict__ A,
                                           const bf16* __restrict__ B,
                                           bf16* sA, bf16* sB,
                                           int row0, int col0, int kt, int tid) {
    int buf = kt % 3;
#pragma unroll
    for (int j = 0; j < 2; j++) {
        int i = tid + 256 * j;
        int r = i >> 2, q = i & 3;
        const bf16* src = A + (size_t)(row0 + r) * KE + kt * 32 + q * 8;
        uint32_t dst = smem_to_u32(sA + buf * STAGE_ELEMS + r * ROWP + q * 8);
        CP_ASYNC16(dst, src);
    }
#pragma unroll
    for (int j = 0; j < 2; j++) {
        int i = tid + 256 * j;
        int r = i >> 2, q = i & 3;
        const bf16* src = B + (size_t)(col0 + r) * KE + kt * 32 + q * 8;
        uint32_t dst = smem_to_u32(sB + buf * STAGE_ELEMS + r * ROWP + q * 8);
        CP_ASYNC16(dst, src);
    }
}

template <int KE>
__global__ void __launch_bounds__(256, 2)
mma_gemm_kernel(const bf16* __restrict__ A, const bf16* __restrict__ B,
                const float* __restrict__ bias, float* __restrict__ C,
                int Mstore, int doRelu) {
    extern __shared__ bf16 sm[];
    bf16* sA = sm;                      // [3][128][ROWP]
    bf16* sB = sm + 3 * STAGE_ELEMS;    // [3][128][ROWP]

    int tid  = threadIdx.x;
    int lane = tid & 31;
    int warp = tid >> 5;
    int wm = warp >> 1, wn = warp & 1;
    int g = lane >> 2, c = lane & 3;

    int row0 = blockIdx.y * 128;
    int col0 = blockIdx.x * 128;

    float acc[2][8][4];
#pragma unroll
    for (int i = 0; i < 2; i++)
#pragma unroll
        for (int j = 0; j < 8; j++)
#pragma unroll
            for (int t = 0; t < 4; t++) acc[i][j][t] = 0.f;

    const int NK = KE / 32;

    gemm_issue<KE>(A, B, sA, sB, row0, col0, 0, tid);
    CP_COMMIT();
    gemm_issue<KE>(A, B, sA, sB, row0, col0, 1, tid);
    CP_COMMIT();

    for (int kt = 0; kt < NK; kt++) {
        int buf = kt % 3;
        CP_WAIT1();
        __syncthreads();

        const bf16* bufA = sA + buf * STAGE_ELEMS;
        const bf16* bufB = sB + buf * STAGE_ELEMS;
#pragma unroll
        for (int ks = 0; ks < 2; ks++) {
            int kb = ks * 16 + c * 2;
            unsigned af[2][4];
#pragma unroll
            for (int i = 0; i < 2; i++) {
                const bf16* pa = bufA + (wm * 32 + i * 16 + g) * ROWP + kb;
                af[i][0] = *(const unsigned*)pa;
                af[i][1] = *(const unsigned*)(pa + 8 * ROWP);
                af[i][2] = *(const unsigned*)(pa + 8);
                af[i][3] = *(const unsigned*)(pa + 8 * ROWP + 8);
            }
#pragma unroll
            for (int j = 0; j < 8; j++) {
                const bf16* pb = bufB + (wn * 64 + j * 8 + g) * ROWP + kb;
                unsigned bfr[2];
                bfr[0] = *(const unsigned*)pb;
                bfr[1] = *(const unsigned*)(pb + 8);
                MMA_BF16(acc[0][j], af[0], bfr);
                MMA_BF16(acc[1][j], af[1], bfr);
            }
        }

        if (kt + 2 < NK)
            gemm_issue<KE>(A, B, sA, sB, row0, col0, kt + 2, tid);
        CP_COMMIT();   // empty commits at tail keep group numbering aligned
    }

    // epilogue
#pragma unroll
    for (int i = 0; i < 2; i++) {
        int r0 = row0 + wm * 32 + i * 16 + g;
        int r1 = r0 + 8;
#pragma unroll
        for (int j = 0; j < 8; j++) {
            int col = col0 + wn * 64 + j * 8 + c * 2;
            float bx = bias[col], by = bias[col + 1];
            float2 v0 = make_float2(acc[i][j][0] + bx, acc[i][j][1] + by);
            float2 v1 = make_float2(acc[i][j][2] + bx, acc[i][j][3] + by);
            if (doRelu) {
                v0.x = fmaxf(v0.x, 0.f); v0.y = fmaxf(v0.y, 0.f);
                v1.x = fmaxf(v1.x, 0.f); v1.y = fmaxf(v1.y, 0.f);
            }
            if (r0 < Mstore) *(float2*)&C[(size_t)r0 * 256 + col] = v0;
            if (r1 < Mstore) *(float2*)&C[(size_t)r1 * 256 + col] = v1;
        }
    }
}

#define SMEM_GEMM (6 * STAGE_ELEMS * (int)sizeof(bf16))   // 61440

// ---------------- launch ----------------
extern "C" void kernel_launch(void* const* d_in, const int* in_sizes, int n_in,
                              void* d_out, int out_size) {
    const float* x   = (const float*)d_in[0];
    const void*  ei  = d_in[1];
    const float* W1  = (const float*)d_in[2];
    const float* b1  = (const float*)d_in[3];
    const float* W2  = (const float*)d_in[4];
    const float* b2  = (const float*)d_in[5];
    float*       out = (float*)d_out;

    bf16 *a1, *a2, *w1e, *w2e;
    float *h;
    cudaGetSymbolAddress((void**)&a1,  g_a1);
    cudaGetSymbolAddress((void**)&a2,  g_a2);
    cudaGetSymbolAddress((void**)&h,   g_h);
    cudaGetSymbolAddress((void**)&w1e, g_w1e);
    cudaGetSymbolAddress((void**)&w2e, g_w2e);

    cudaFuncSetAttribute(mma_gemm_kernel<3 * IN_CH>,
                         cudaFuncAttributeMaxDynamicSharedMemorySize, SMEM_GEMM);
    cudaFuncSetAttribute(mma_gemm_kernel<3 * HID>,
                         cudaFuncAttributeMaxDynamicSharedMemorySize, SMEM_GEMM);

    // graph build + weight split
    detect_kernel<<<1, 128>>>((const int*)ei);
    zero_cnt_kernel<<<(N_NODES + 255) / 256, 256>>>();
    hist_kernel<<<(N_EDGES + 255) / 256, 256>>>(ei);
    splitW_kernel<<<(IN_CH * 256 + 255) / 256, 256>>>(W1, IN_CH, w1e);
    splitW_kernel<<<(HID * 256 + 255) / 256, 256>>>(W2, HID, w2e);
    blocksum_kernel<<<NBLK, 256>>>();
    scanb_kernel<<<1, 256>>>();
    fillptr_kernel<<<NBLK, 256>>>();
    fill_kernel<<<(N_EDGES + 255) / 256, 256>>>(ei);

    // layer 1: p = A_norm @ x (ext split) ; h = relu(p @ W1 + b1)
    agg_kernel<IN_CH><<<N_NODES, 128>>>(x, a1);
    mma_gemm_kernel<3 * IN_CH><<<dim3(2, MPAD / 128), 256, SMEM_GEMM>>>(a1, w1e, b1, h, MPAD, 1);

    // layer 2: q = A_norm @ h (ext split) ; out = q @ W2 + b2
    agg_kernel<HID><<<N_NODES, 128>>>(h, a2);
    mma_gemm_kernel<3 * HID><<<dim3(2, MPAD / 128), 256, SMEM_GEMM>>>(a2, w2e, b2, out, N_NODES, 0);
}

// round 7
// speedup vs baseline: 2.1387x; 1.1949x over previous
#include <cuda_runtime.h>
#include <cuda_fp16.h>
#include <math.h>
#include <stdint.h>

#define N_NODES 50000
#define N_EDGES 800000
#define IN_CH   128
#define HID     256
#define MPAD    50048   // 391 * 128
#define NBLK    ((N_NODES + 255) / 256)   // 196

// ---------------- scratch (device globals; zero-initialized bss) ----------------
__device__ int   g_is64;
__device__ int   g_cnt[N_NODES];
__device__ int   g_bsum[NBLK];
__device__ int   g_boff[NBLK];
__device__ int   g_rowptr[N_NODES + 1];
__device__ int   g_cursor[N_NODES];
__device__ int   g_col[N_EDGES];
__device__ float g_dinv[N_NODES];

// fp16 2-term split: A_ext = [ah | al], B_ext = [bh | bh]
__device__ __half g_a1[(size_t)MPAD * (2 * IN_CH)];  // layer-1 A_ext (pad rows stay 0)
__device__ __half g_a2[(size_t)MPAD * (2 * HID)];    // layer-2 A_ext (pad rows stay 0)
__device__ __half g_h[(size_t)MPAD * HID];           // relu(p@W1+b1), fp16
__device__ __half g_w1e[HID * (2 * IN_CH)];          // W1^T ext [256][256]
__device__ __half g_w2e[HID * (2 * HID)];            // W2^T ext [256][512]

// ---------------- helpers ----------------
__device__ __forceinline__ uint32_t smem_to_u32(const void* p) {
    uint32_t a;
    asm("{ .reg .u64 t; cvta.to.shared.u64 t, %1; cvt.u32.u64 %0, t; }" : "=r"(a) : "l"(p));
    return a;
}
#define CP_ASYNC16(dst, src) \
    asm volatile("cp.async.cg.shared.global [%0], [%1], 16;" :: "r"(dst), "l"(src))
#define CP_COMMIT() asm volatile("cp.async.commit_group;" ::: "memory")
#define CP_WAIT1()  asm volatile("cp.async.wait_group 1;" ::: "memory")

#define MMA_F16(acc, a, b) \
    asm volatile("mma.sync.aligned.m16n8k16.row.col.f32.f16.f16.f32 " \
                 "{%0,%1,%2,%3},{%4,%5,%6,%7},{%8,%9},{%0,%1,%2,%3};" \
                 : "+f"(acc[0]), "+f"(acc[1]), "+f"(acc[2]), "+f"(acc[3]) \
                 : "r"(a[0]), "r"(a[1]), "r"(a[2]), "r"(a[3]), "r"(b[0]), "r"(b[1]))

// ---------------- dtype detection ----------------
__global__ void detect_kernel(const int* __restrict__ ei_raw) {
    __shared__ int bad;
    if (threadIdx.x == 0) bad = 0;
    __syncthreads();
    if (ei_raw[2 * threadIdx.x + 1] != 0) bad = 1;
    __syncthreads();
    if (threadIdx.x == 0) g_is64 = (bad == 0);
}
__device__ __forceinline__ int load_edge(const void* ei, long long pos) {
    if (g_is64) return (int)((const long long*)ei)[pos];
    return ((const int*)ei)[pos];
}

// ---------------- graph preprocessing ----------------
__global__ void zero_cnt_kernel() {
    int i = blockIdx.x * blockDim.x + threadIdx.x;
    if (i < N_NODES) g_cnt[i] = 0;
}
__global__ void hist_kernel(const void* __restrict__ ei) {
    int e = blockIdx.x * blockDim.x + threadIdx.x;
    if (e < N_EDGES) atomicAdd(&g_cnt[load_edge(ei, (long long)N_EDGES + e)], 1);
}
__global__ void __launch_bounds__(256) blocksum_kernel() {
    __shared__ int sh[256];
    int i = blockIdx.x * 256 + threadIdx.x;
    int v = (i < N_NODES) ? g_cnt[i] : 0;
    sh[threadIdx.x] = v;
    __syncthreads();
    for (int off = 128; off > 0; off >>= 1) {
        if (threadIdx.x < off) sh[threadIdx.x] += sh[threadIdx.x + off];
        __syncthreads();
    }
    if (threadIdx.x == 0) g_bsum[blockIdx.x] = sh[0];
}
__global__ void __launch_bounds__(256) scanb_kernel() {
    __shared__ int sh[256];
    int t = threadIdx.x;
    int v = (t < NBLK) ? g_bsum[t] : 0;
    sh[t] = v;
    __syncthreads();
    for (int off = 1; off < 256; off <<= 1) {
        int u = (t >= off) ? sh[t - off] : 0;
        __syncthreads();
        sh[t] += u;
        __syncthreads();
    }
    if (t < NBLK) g_boff[t] = sh[t] - v;
}
__global__ void __launch_bounds__(256) fillptr_kernel() {
    __shared__ int sh[256];
    int i = blockIdx.x * 256 + threadIdx.x;
    int c = (i < N_NODES) ? g_cnt[i] : 0;
    sh[threadIdx.x] = c;
    __syncthreads();
    for (int off = 1; off < 256; off <<= 1) {
        int u = (threadIdx.x >= off) ? sh[threadIdx.x - off] : 0;
        __syncthreads();
        sh[threadIdx.x] += u;
        __syncthreads();
    }
    if (i < N_NODES) {
        int excl = sh[threadIdx.x] - c + g_boff[blockIdx.x];
        g_rowptr[i] = excl;
        g_cursor[i] = excl;
        g_dinv[i]   = rsqrtf((float)(c + 1));
    }
    if (i == 0) g_rowptr[N_NODES] = N_EDGES;
}
__global__ void fill_kernel(const void* __restrict__ ei) {
    int e = blockIdx.x * blockDim.x + threadIdx.x;
    if (e < N_EDGES) {
        int s = load_edge(ei, e);
        int d = load_edge(ei, (long long)N_EDGES + e);
        int pos = atomicAdd(&g_cursor[d], 1);
        g_col[pos] = s;
    }
}

// ---------------- W round+transpose: W [K][256] fp32 -> Bex [256][2K] fp16 [bh|bh] --------
__global__ void splitW_kernel(const float* __restrict__ W, int K, __half* __restrict__ Bex) {
    int idx = blockIdx.x * 256 + threadIdx.x;
    if (idx < K * 256) {
        int k = idx >> 8, n = idx & 255;
        __half h = __float2half_rn(W[idx]);
        size_t rb = (size_t)n * 2 * K;
        Bex[rb + k]     = h;
        Bex[rb + K + k] = h;
    }
}

// ---------------- layer-1 aggregation: fp32 gather -> A_ext [ah|al] fp16 (F=128) ----------
__global__ void __launch_bounds__(128)
agg1_kernel(const float* __restrict__ feat, __half* __restrict__ Aex) {
    __shared__ int   s_idx[32];
    __shared__ float s_w[32];
    int v   = blockIdx.x;
    int tid = threadIdx.x;
    int beg = g_rowptr[v];
    int end = g_rowptr[v + 1];

    float acc = 0.f;
    for (int cs = beg; cs < end; cs += 32) {
        int n = end - cs; if (n > 32) n = 32;
        if (tid < n) {
            int s = g_col[cs + tid];
            s_idx[tid] = s;
            s_w[tid]   = g_dinv[s];
        }
        __syncthreads();
        for (int j = 0; j < n; j++)
            acc += s_w[j] * feat[(size_t)s_idx[j] * IN_CH + tid];
        __syncthreads();
    }

    float dv = g_dinv[v];
    float val = dv * acc + dv * dv * feat[(size_t)v * IN_CH + tid];
    __half hh = __float2half_rn(val);
    __half hl = __float2half_rn(val - __half2float(hh));
    size_t rb = (size_t)v * (2 * IN_CH);
    Aex[rb + tid]          = hh;
    Aex[rb + IN_CH + tid]  = hl;
}

// ---------------- layer-2 aggregation: fp16 half2 gather -> A_ext [ah|al] fp16 (F=256) ----
__global__ void __launch_bounds__(128)
agg2_kernel(const __half* __restrict__ feat, __half* __restrict__ Aex) {
    __shared__ int   s_idx[32];
    __shared__ float s_w[32];
    int v   = blockIdx.x;
    int tid = threadIdx.x;
    int beg = g_rowptr[v];
    int end = g_rowptr[v + 1];

    const __half2* f2 = (const __half2*)feat;   // 128 half2 per row
    float ax = 0.f, ay = 0.f;
    for (int cs = beg; cs < end; cs += 32) {
        int n = end - cs; if (n > 32) n = 32;
        if (tid < n) {
            int s = g_col[cs + tid];
            s_idx[tid] = s;
            s_w[tid]   = g_dinv[s];
        }
        __syncthreads();
        for (int j = 0; j < n; j++) {
            float2 f = __half22float2(f2[(size_t)s_idx[j] * 128 + tid]);
            float w = s_w[j];
            ax += w * f.x;
            ay += w * f.y;
        }
        __syncthreads();
    }

    float dv = g_dinv[v];
    float2 self = __half22float2(f2[(size_t)v * 128 + tid]);
    float vx = dv * ax + dv * dv * self.x;
    float vy = dv * ay + dv * dv * self.y;
    __half2 hh = __floats2half2_rn(vx, vy);
    float2 hf = __half22float2(hh);
    __half2 hl = __floats2half2_rn(vx - hf.x, vy - hf.y);
    size_t rb = (size_t)v * (2 * HID);
    ((__half2*)(Aex + rb))[tid]        = hh;
    ((__half2*)(Aex + rb + HID))[tid]  = hl;
}

// ---------------- pipelined mma.sync fp16 GEMM ----------------
// C[M,256] = A_ext[M,KE] @ B_ext^T[256,KE] (+bias, relu)
// Block 128x128, BK=32, 3-stage cp.async pipeline, 8 warps (4m x 2n),
// warp tile 32x64, mma m16n8k16. smem rows padded to 40 fp16 (conflict-free).
#define ROWP 40
#define STAGE_ELEMS (128 * ROWP)

template <int KE>
__device__ __forceinline__ void gemm_issue(const __half* __restrict__ A,
                                           const __half* __restrict__ B,
                                           __half* sA, __half* sB,
                                           int row0, int col0, int kt, int tid) {
    int buf = kt % 3;
#pragma unroll
    for (int j = 0; j < 2; j++) {
        int i = tid + 256 * j;
        int r = i >> 2, q = i & 3;
        const __half* src = A + (size_t)(row0 + r) * KE + kt * 32 + q * 8;
        uint32_t dst = smem_to_u32(sA + buf * STAGE_ELEMS + r * ROWP + q * 8);
        CP_ASYNC16(dst, src);
    }
#pragma unroll
    for (int j = 0; j < 2; j++) {
        int i = tid + 256 * j;
        int r = i >> 2, q = i & 3;
        const __half* src = B + (size_t)(col0 + r) * KE + kt * 32 + q * 8;
        uint32_t dst = smem_to_u32(sB + buf * STAGE_ELEMS + r * ROWP + q * 8);
        CP_ASYNC16(dst, src);
    }
}

template <int KE, bool HALF_OUT>
__global__ void __launch_bounds__(256, 2)
mma_gemm_kernel(const __half* __restrict__ A, const __half* __restrict__ B,
                const float* __restrict__ bias, float* __restrict__ Cf,
                __half* __restrict__ Ch, int Mstore, int doRelu) {
    extern __shared__ __half sm[];
    __half* sA = sm;                      // [3][128][ROWP]
    __half* sB = sm + 3 * STAGE_ELEMS;    // [3][128][ROWP]

    int tid  = threadIdx.x;
    int lane = tid & 31;
    int warp = tid >> 5;
    int wm = warp >> 1, wn = warp & 1;
    int g = lane >> 2, c = lane & 3;

    int row0 = blockIdx.y * 128;
    int col0 = blockIdx.x * 128;

    float acc[2][8][4];
#pragma unroll
    for (int i = 0; i < 2; i++)
#pragma unroll
        for (int j = 0; j < 8; j++)
#pragma unroll
            for (int t = 0; t < 4; t++) acc[i][j][t] = 0.f;

    const int NK = KE / 32;

    gemm_issue<KE>(A, B, sA, sB, row0, col0, 0, tid);
    CP_COMMIT();
    gemm_issue<KE>(A, B, sA, sB, row0, col0, 1, tid);
    CP_COMMIT();

    for (int kt = 0; kt < NK; kt++) {
        int buf = kt % 3;
        CP_WAIT1();
        __syncthreads();

        const __half* bufA = sA + buf * STAGE_ELEMS;
        const __half* bufB = sB + buf * STAGE_ELEMS;
#pragma unroll
        for (int ks = 0; ks < 2; ks++) {
            int kb = ks * 16 + c * 2;
            unsigned af[2][4];
#pragma unroll
            for (int i = 0; i < 2; i++) {
                const __half* pa = bufA + (wm * 32 + i * 16 + g) * ROWP + kb;
                af[i][0] = *(const unsigned*)pa;
                af[i][1] = *(const unsigned*)(pa + 8 * ROWP);
                af[i][2] = *(const unsigned*)(pa + 8);
                af[i][3] = *(const unsigned*)(pa + 8 * ROWP + 8);
            }
#pragma unroll
            for (int j = 0; j < 8; j++) {
                const __half* pb = bufB + (wn * 64 + j * 8 + g) * ROWP + kb;
                unsigned bfr[2];
                bfr[0] = *(const unsigned*)pb;
                bfr[1] = *(const unsigned*)(pb + 8);
                MMA_F16(acc[0][j], af[0], bfr);
                MMA_F16(acc[1][j], af[1], bfr);
            }
        }

        if (kt + 2 < NK)
            gemm_issue<KE>(A, B, sA, sB, row0, col0, kt + 2, tid);
        CP_COMMIT();   // empty commits at tail keep group numbering aligned
    }

    // epilogue
#pragma unroll
    for (int i = 0; i < 2; i++) {
        int r0 = row0 + wm * 32 + i * 16 + g;
        int r1 = r0 + 8;
#pragma unroll
        for (int j = 0; j < 8; j++) {
            int col = col0 + wn * 64 + j * 8 + c * 2;
            float bx = bias[col], by = bias[col + 1];
            float2 v0 = make_float2(acc[i][j][0] + bx, acc[i][j][1] + by);
            float2 v1 = make_float2(acc[i][j][2] + bx, acc[i][j][3] + by);
            if (doRelu) {
                v0.x = fmaxf(v0.x, 0.f); v0.y = fmaxf(v0.y, 0.f);
                v1.x = fmaxf(v1.x, 0.f); v1.y = fmaxf(v1.y, 0.f);
            }
            if (HALF_OUT) {
                if (r0 < Mstore) *(__half2*)&Ch[(size_t)r0 * 256 + col] = __floats2half2_rn(v0.x, v0.y);
                if (r1 < Mstore) *(__half2*)&Ch[(size_t)r1 * 256 + col] = __floats2half2_rn(v1.x, v1.y);
            } else {
                if (r0 < Mstore) *(float2*)&Cf[(size_t)r0 * 256 + col] = v0;
                if (r1 < Mstore) *(float2*)&Cf[(size_t)r1 * 256 + col] = v1;
            }
        }
    }
}

#define SMEM_GEMM (6 * STAGE_ELEMS * (int)sizeof(__half))   // 61440

// ---------------- launch ----------------
extern "C" void kernel_launch(void* const* d_in, const int* in_sizes, int n_in,
                              void* d_out, int out_size) {
    const float* x   = (const float*)d_in[0];
    const void*  ei  = d_in[1];
    const float* W1  = (const float*)d_in[2];
    const float* b1  = (const float*)d_in[3];
    const float* W2  = (const float*)d_in[4];
    const float* b2  = (const float*)d_in[5];
    float*       out = (float*)d_out;

    __half *a1, *a2, *w1e, *w2e, *h;
    cudaGetSymbolAddress((void**)&a1,  g_a1);
    cudaGetSymbolAddress((void**)&a2,  g_a2);
    cudaGetSymbolAddress((void**)&h,   g_h);
    cudaGetSymbolAddress((void**)&w1e, g_w1e);
    cudaGetSymbolAddress((void**)&w2e, g_w2e);

    cudaFuncSetAttribute(mma_gemm_kernel<2 * IN_CH, true>,
                         cudaFuncAttributeMaxDynamicSharedMemorySize, SMEM_GEMM);
    cudaFuncSetAttribute(mma_gemm_kernel<2 * HID, false>,
                         cudaFuncAttributeMaxDynamicSharedMemorySize, SMEM_GEMM);

    // graph build + weight prep
    detect_kernel<<<1, 128>>>((const int*)ei);
    zero_cnt_kernel<<<(N_NODES + 255) / 256, 256>>>();
    hist_kernel<<<(N_EDGES + 255) / 256, 256>>>(ei);
    splitW_kernel<<<(IN_CH * 256 + 255) / 256, 256>>>(W1, IN_CH, w1e);
    splitW_kernel<<<(HID * 256 + 255) / 256, 256>>>(W2, HID, w2e);
    blocksum_kernel<<<NBLK, 256>>>();
    scanb_kernel<<<1, 256>>>();
    fillptr_kernel<<<NBLK, 256>>>();
    fill_kernel<<<(N_EDGES + 255) / 256, 256>>>(ei);

    // layer 1: p = A_norm @ x (fp16 split) ; h = relu(p @ W1 + b1) -> fp16
    agg1_kernel<<<N_NODES, 128>>>(x, a1);
    mma_gemm_kernel<2 * IN_CH, true><<<dim3(2, MPAD / 128), 256, SMEM_GEMM>>>(
        a1, w1e, b1, nullptr, h, MPAD, 1);

    // layer 2: q = A_norm @ h (fp16 split) ; out = q @ W2 + b2 -> fp32
    agg2_kernel<<<N_NODES, 128>>>(h, a2);
    mma_gemm_kernel<2 * HID, false><<<dim3(2, MPAD / 128), 256, SMEM_GEMM>>>(
        a2, w2e, b2, out, nullptr, N_NODES, 0);
}

// round 8
// speedup vs baseline: 2.7477x; 1.2848x over previous
#include <cuda_runtime.h>
#include <cuda_fp16.h>
#include <math.h>
#include <stdint.h>

#define N_NODES 50000
#define N_EDGES 800000
#define IN_CH   128
#define HID     256
#define MPAD    50048   // 391 * 128
#define NBLK    ((N_NODES + 255) / 256)   // 196

// ---------------- scratch (device globals; zero-initialized bss) ----------------
__device__ int   g_is64;
__device__ int   g_cnt[N_NODES];
__device__ int   g_bsum[NBLK];
__device__ int   g_boff[NBLK];
__device__ int   g_rowptr[N_NODES + 1];
__device__ int   g_cursor[N_NODES];
__device__ int   g_col[N_EDGES];
__device__ float g_dinv[N_NODES];

__device__ __half g_x16[(size_t)N_NODES * IN_CH];   // x rounded to fp16
__device__ __half g_a1[(size_t)MPAD * IN_CH];       // agg1 out (pad rows stay 0)
__device__ __half g_h[(size_t)MPAD * HID];          // relu(a1@W1+b1), fp16
__device__ __half g_a2[(size_t)MPAD * HID];         // agg2 out (pad rows stay 0)
__device__ __half g_w1t[HID * IN_CH];               // W1^T fp16 [256][128]
__device__ __half g_w2t[HID * HID];                 // W2^T fp16 [256][256]

// ---------------- helpers ----------------
__device__ __forceinline__ uint32_t smem_to_u32(const void* p) {
    uint32_t a;
    asm("{ .reg .u64 t; cvta.to.shared.u64 t, %1; cvt.u32.u64 %0, t; }" : "=r"(a) : "l"(p));
    return a;
}
#define CP_ASYNC16(dst, src) \
    asm volatile("cp.async.cg.shared.global [%0], [%1], 16;" :: "r"(dst), "l"(src))
#define CP_COMMIT() asm volatile("cp.async.commit_group;" ::: "memory")
#define CP_WAIT1()  asm volatile("cp.async.wait_group 1;" ::: "memory")

#define MMA_F16(acc, a, b) \
    asm volatile("mma.sync.aligned.m16n8k16.row.col.f32.f16.f16.f32 " \
                 "{%0,%1,%2,%3},{%4,%5,%6,%7},{%8,%9},{%0,%1,%2,%3};" \
                 : "+f"(acc[0]), "+f"(acc[1]), "+f"(acc[2]), "+f"(acc[3]) \
                 : "r"(a[0]), "r"(a[1]), "r"(a[2]), "r"(a[3]), "r"(b[0]), "r"(b[1]))

// ---------------- dtype detection ----------------
__global__ void detect_kernel(const int* __restrict__ ei_raw) {
    __shared__ int bad;
    if (threadIdx.x == 0) bad = 0;
    __syncthreads();
    if (ei_raw[2 * threadIdx.x + 1] != 0) bad = 1;
    __syncthreads();
    if (threadIdx.x == 0) g_is64 = (bad == 0);
}
__device__ __forceinline__ int load_edge(const void* ei, long long pos) {
    if (g_is64) return (int)((const long long*)ei)[pos];
    return ((const int*)ei)[pos];
}

// ---------------- graph preprocessing ----------------
__global__ void zero_cnt_kernel() {
    int i = blockIdx.x * blockDim.x + threadIdx.x;
    if (i < N_NODES) g_cnt[i] = 0;
}
__global__ void hist_kernel(const void* __restrict__ ei) {
    int e = blockIdx.x * blockDim.x + threadIdx.x;
    if (e < N_EDGES) atomicAdd(&g_cnt[load_edge(ei, (long long)N_EDGES + e)], 1);
}
__global__ void __launch_bounds__(256) blocksum_kernel() {
    __shared__ int sh[256];
    int i = blockIdx.x * 256 + threadIdx.x;
    int v = (i < N_NODES) ? g_cnt[i] : 0;
    sh[threadIdx.x] = v;
    __syncthreads();
    for (int off = 128; off > 0; off >>= 1) {
        if (threadIdx.x < off) sh[threadIdx.x] += sh[threadIdx.x + off];
        __syncthreads();
    }
    if (threadIdx.x == 0) g_bsum[blockIdx.x] = sh[0];
}
__global__ void __launch_bounds__(256) scanb_kernel() {
    __shared__ int sh[256];
    int t = threadIdx.x;
    int v = (t < NBLK) ? g_bsum[t] : 0;
    sh[t] = v;
    __syncthreads();
    for (int off = 1; off < 256; off <<= 1) {
        int u = (t >= off) ? sh[t - off] : 0;
        __syncthreads();
        sh[t] += u;
        __syncthreads();
    }
    if (t < NBLK) g_boff[t] = sh[t] - v;
}
__global__ void __launch_bounds__(256) fillptr_kernel() {
    __shared__ int sh[256];
    int i = blockIdx.x * 256 + threadIdx.x;
    int c = (i < N_NODES) ? g_cnt[i] : 0;
    sh[threadIdx.x] = c;
    __syncthreads();
    for (int off = 1; off < 256; off <<= 1) {
        int u = (threadIdx.x >= off) ? sh[threadIdx.x - off] : 0;
        __syncthreads();
        sh[threadIdx.x] += u;
        __syncthreads();
    }
    if (i < N_NODES) {
        int excl = sh[threadIdx.x] - c + g_boff[blockIdx.x];
        g_rowptr[i] = excl;
        g_cursor[i] = excl;
        g_dinv[i]   = rsqrtf((float)(c + 1));
    }
    if (i == 0) g_rowptr[N_NODES] = N_EDGES;
}
__global__ void fill_kernel(const void* __restrict__ ei) {
    int e = blockIdx.x * blockDim.x + threadIdx.x;
    if (e < N_EDGES) {
        int s = load_edge(ei, e);
        int d = load_edge(ei, (long long)N_EDGES + e);
        int pos = atomicAdd(&g_cursor[d], 1);
        g_col[pos] = s;
    }
}

// ---------------- x -> fp16 ----------------
__global__ void x2h_kernel(const float* __restrict__ x, __half* __restrict__ xh) {
    int i = blockIdx.x * blockDim.x + threadIdx.x;   // one float4 per thread
    if (i < N_NODES * IN_CH / 4) {
        float4 v = ((const float4*)x)[i];
        ((__half2*)xh)[2 * i]     = __floats2half2_rn(v.x, v.y);
        ((__half2*)xh)[2 * i + 1] = __floats2half2_rn(v.z, v.w);
    }
}

// ---------------- W round+transpose: W [K][256] fp32 -> WT [256][K] fp16 ----------------
__global__ void roundW_kernel(const float* __restrict__ W, int K, __half* __restrict__ WT) {
    int idx = blockIdx.x * 256 + threadIdx.x;
    if (idx < K * 256) {
        int k = idx >> 8, n = idx & 255;
        WT[(size_t)n * K + k] = __float2half_rn(W[idx]);
    }
}

// ---------------- layer-1 aggregation: fp16 half2 gather (F=128, 64 threads) ----------
__global__ void __launch_bounds__(64)
agg1_kernel(const __half* __restrict__ feat, __half* __restrict__ A) {
    __shared__ int   s_idx[32];
    __shared__ float s_w[32];
    int v   = blockIdx.x;
    int tid = threadIdx.x;
    int beg = g_rowptr[v];
    int end = g_rowptr[v + 1];

    const __half2* f2 = (const __half2*)feat;   // 64 half2 per row
    float ax = 0.f, ay = 0.f;
    for (int cs = beg; cs < end; cs += 32) {
        int n = end - cs; if (n > 32) n = 32;
        if (tid < n) {
            int s = g_col[cs + tid];
            s_idx[tid] = s;
            s_w[tid]   = g_dinv[s];
        }
        __syncthreads();
        for (int j = 0; j < n; j++) {
            float2 f = __half22float2(f2[(size_t)s_idx[j] * 64 + tid]);
            float w = s_w[j];
            ax += w * f.x;
            ay += w * f.y;
        }
        __syncthreads();
    }

    float dv = g_dinv[v];
    float2 self = __half22float2(f2[(size_t)v * 64 + tid]);
    float vx = dv * ax + dv * dv * self.x;
    float vy = dv * ay + dv * dv * self.y;
    ((__half2*)(A + (size_t)v * IN_CH))[tid] = __floats2half2_rn(vx, vy);
}

// ---------------- layer-2 aggregation: fp16 half2 gather (F=256, 128 threads) ----------
__global__ void __launch_bounds__(128)
agg2_kernel(const __half* __restrict__ feat, __half* __restrict__ A) {
    __shared__ int   s_idx[32];
    __shared__ float s_w[32];
    int v   = blockIdx.x;
    int tid = threadIdx.x;
    int beg = g_rowptr[v];
    int end = g_rowptr[v + 1];

    const __half2* f2 = (const __half2*)feat;   // 128 half2 per row
    float ax = 0.f, ay = 0.f;
    for (int cs = beg; cs < end; cs += 32) {
        int n = end - cs; if (n > 32) n = 32;
        if (tid < n) {
            int s = g_col[cs + tid];
            s_idx[tid] = s;
            s_w[tid]   = g_dinv[s];
        }
        __syncthreads();
        for (int j = 0; j < n; j++) {
            float2 f = __half22float2(f2[(size_t)s_idx[j] * 128 + tid]);
            float w = s_w[j];
            ax += w * f.x;
            ay += w * f.y;
        }
        __syncthreads();
    }

    float dv = g_dinv[v];
    float2 self = __half22float2(f2[(size_t)v * 128 + tid]);
    float vx = dv * ax + dv * dv * self.x;
    float vy = dv * ay + dv * dv * self.y;
    ((__half2*)(A + (size_t)v * HID))[tid] = __floats2half2_rn(vx, vy);
}

// ---------------- pipelined mma.sync fp16 GEMM ----------------
// C[M,256] = A[M,KE] @ B^T[256,KE] (+bias, relu)
// Block 128x128, BK=32, 3-stage cp.async pipeline, 8 warps (4m x 2n),
// warp tile 32x64, mma m16n8k16. smem rows padded to 40 fp16 (conflict-free).
#define ROWP 40
#define STAGE_ELEMS (128 * ROWP)

template <int KE>
__device__ __forceinline__ void gemm_issue(const __half* __restrict__ A,
                                           const __half* __restrict__ B,
                                           __half* sA, __half* sB,
                                           int row0, int col0, int kt, int tid) {
    int buf = kt % 3;
#pragma unroll
    for (int j = 0; j < 2; j++) {
        int i = tid + 256 * j;
        int r = i >> 2, q = i & 3;
        const __half* src = A + (size_t)(row0 + r) * KE + kt * 32 + q * 8;
        uint32_t dst = smem_to_u32(sA + buf * STAGE_ELEMS + r * ROWP + q * 8);
        CP_ASYNC16(dst, src);
    }
#pragma unroll
    for (int j = 0; j < 2; j++) {
        int i = tid + 256 * j;
        int r = i >> 2, q = i & 3;
        const __half* src = B + (size_t)(col0 + r) * KE + kt * 32 + q * 8;
        uint32_t dst = smem_to_u32(sB + buf * STAGE_ELEMS + r * ROWP + q * 8);
        CP_ASYNC16(dst, src);
    }
}

template <int KE, bool HALF_OUT>
__global__ void __launch_bounds__(256, 2)
mma_gemm_kernel(const __half* __restrict__ A, const __half* __restrict__ B,
                const float* __restrict__ bias, float* __restrict__ Cf,
                __half* __restrict__ Ch, int Mstore, int doRelu) {
    extern __shared__ __half sm[];
    __half* sA = sm;                      // [3][128][ROWP]
    __half* sB = sm + 3 * STAGE_ELEMS;    // [3][128][ROWP]

    int tid  = threadIdx.x;
    int lane = tid & 31;
    int warp = tid >> 5;
    int wm = warp >> 1, wn = warp & 1;
    int g = lane >> 2, c = lane & 3;

    int row0 = blockIdx.y * 128;
    int col0 = blockIdx.x * 128;

    float acc[2][8][4];
#pragma unroll
    for (int i = 0; i < 2; i++)
#pragma unroll
        for (int j = 0; j < 8; j++)
#pragma unroll
            for (int t = 0; t < 4; t++) acc[i][j][t] = 0.f;

    const int NK = KE / 32;

    gemm_issue<KE>(A, B, sA, sB, row0, col0, 0, tid);
    CP_COMMIT();
    gemm_issue<KE>(A, B, sA, sB, row0, col0, 1, tid);
    CP_COMMIT();

    for (int kt = 0; kt < NK; kt++) {
        int buf = kt % 3;
        CP_WAIT1();
        __syncthreads();

        const __half* bufA = sA + buf * STAGE_ELEMS;
        const __half* bufB = sB + buf * STAGE_ELEMS;
#pragma unroll
        for (int ks = 0; ks < 2; ks++) {
            int kb = ks * 16 + c * 2;
            unsigned af[2][4];
#pragma unroll
            for (int i = 0; i < 2; i++) {
                const __half* pa = bufA + (wm * 32 + i * 16 + g) * ROWP + kb;
                af[i][0] = *(const unsigned*)pa;
                af[i][1] = *(const unsigned*)(pa + 8 * ROWP);
                af[i][2] = *(const unsigned*)(pa + 8);
                af[i][3] = *(const unsigned*)(pa + 8 * ROWP + 8);
            }
#pragma unroll
            for (int j = 0; j < 8; j++) {
                const __half* pb = bufB + (wn * 64 + j * 8 + g) * ROWP + kb;
                unsigned bfr[2];
                bfr[0] = *(const unsigned*)pb;
                bfr[1] = *(const unsigned*)(pb + 8);
                MMA_F16(acc[0][j], af[0], bfr);
                MMA_F16(acc[1][j], af[1], bfr);
            }
        }

        if (kt + 2 < NK)
            gemm_issue<KE>(A, B, sA, sB, row0, col0, kt + 2, tid);
        CP_COMMIT();   // empty commits at tail keep group numbering aligned
    }

    // epilogue
#pragma unroll
    for (int i = 0; i < 2; i++) {
        int r0 = row0 + wm * 32 + i * 16 + g;
        int r1 = r0 + 8;
#pragma unroll
        for (int j = 0; j < 8; j++) {
            int col = col0 + wn * 64 + j * 8 + c * 2;
            float bx = bias[col], by = bias[col + 1];
            float2 v0 = make_float2(acc[i][j][0] + bx, acc[i][j][1] + by);
            float2 v1 = make_float2(acc[i][j][2] + bx, acc[i][j][3] + by);
            if (doRelu) {
                v0.x = fmaxf(v0.x, 0.f); v0.y = fmaxf(v0.y, 0.f);
                v1.x = fmaxf(v1.x, 0.f); v1.y = fmaxf(v1.y, 0.f);
            }
            if (HALF_OUT) {
                if (r0 < Mstore) *(__half2*)&Ch[(size_t)r0 * 256 + col] = __floats2half2_rn(v0.x, v0.y);
                if (r1 < Mstore) *(__half2*)&Ch[(size_t)r1 * 256 + col] = __floats2half2_rn(v1.x, v1.y);
            } else {
                if (r0 < Mstore) *(float2*)&Cf[(size_t)r0 * 256 + col] = v0;
                if (r1 < Mstore) *(float2*)&Cf[(size_t)r1 * 256 + col] = v1;
            }
        }
    }
}

#define SMEM_GEMM (6 * STAGE_ELEMS * (int)sizeof(__half))   // 61440

// ---------------- launch ----------------
extern "C" void kernel_launch(void* const* d_in, const int* in_sizes, int n_in,
                              void* d_out, int out_size) {
    const float* x   = (const float*)d_in[0];
    const void*  ei  = d_in[1];
    const float* W1  = (const float*)d_in[2];
    const float* b1  = (const float*)d_in[3];
    const float* W2  = (const float*)d_in[4];
    const float* b2  = (const float*)d_in[5];
    float*       out = (float*)d_out;

    __half *x16, *a1, *a2, *w1t, *w2t, *h;
    cudaGetSymbolAddress((void**)&x16, g_x16);
    cudaGetSymbolAddress((void**)&a1,  g_a1);
    cudaGetSymbolAddress((void**)&a2,  g_a2);
    cudaGetSymbolAddress((void**)&h,   g_h);
    cudaGetSymbolAddress((void**)&w1t, g_w1t);
    cudaGetSymbolAddress((void**)&w2t, g_w2t);

    cudaFuncSetAttribute(mma_gemm_kernel<IN_CH, true>,
                         cudaFuncAttributeMaxDynamicSharedMemorySize, SMEM_GEMM);
    cudaFuncSetAttribute(mma_gemm_kernel<HID, false>,
                         cudaFuncAttributeMaxDynamicSharedMemorySize, SMEM_GEMM);

    // graph build + operand prep
    detect_kernel<<<1, 128>>>((const int*)ei);
    zero_cnt_kernel<<<(N_NODES + 255) / 256, 256>>>();
    hist_kernel<<<(N_EDGES + 255) / 256, 256>>>(ei);
    x2h_kernel<<<(N_NODES * IN_CH / 4 + 255) / 256, 256>>>(x, x16);
    roundW_kernel<<<(IN_CH * 256 + 255) / 256, 256>>>(W1, IN_CH, w1t);
    roundW_kernel<<<(HID * 256 + 255) / 256, 256>>>(W2, HID, w2t);
    blocksum_kernel<<<NBLK, 256>>>();
    scanb_kernel<<<1, 256>>>();
    fillptr_kernel<<<NBLK, 256>>>();
    fill_kernel<<<(N_EDGES + 255) / 256, 256>>>(ei);

    // layer 1: a1 = A_norm @ x16 ; h = relu(a1 @ W1 + b1) -> fp16
    agg1_kernel<<<N_NODES, 64>>>(x16, a1);
    mma_gemm_kernel<IN_CH, true><<<dim3(2, MPAD / 128), 256, SMEM_GEMM>>>(
        a1, w1t, b1, nullptr, h, MPAD, 1);

    // layer 2: a2 = A_norm @ h ; out = a2 @ W2 + b2 -> fp32
    agg2_kernel<<<N_NODES, 128>>>(h, a2);
    mma_gemm_kernel<HID, false><<<dim3(2, MPAD / 128), 256, SMEM_GEMM>>>(
        a2, w2t, b2, out, nullptr, N_NODES, 0);
}